// round 3
// baseline (speedup 1.0000x reference)
#include <cuda_runtime.h>
#include <math.h>

#define POOLK 7
#define HH 50
#define WW 50
#define CC 512
#define NROIS 300
#define NPOS (HH * WW)
#define NBINS (POOLK * POOLK)

// Device-global scratch (no allocations allowed).
__device__ float g_fmax[NPOS];            // 10 KB, channel-max map
__device__ float g_pool[NROIS * NBINS];   // 58.8 KB, per-(roi,bin) maxima

// ---------------------------------------------------------------------------
// Kernel 1: fmax[h][w] = max_c feature_maps[h][w][c]
// One warp per spatial position; 512 contiguous floats -> 4 x float4 per lane.
// ---------------------------------------------------------------------------
__global__ void __launch_bounds__(256) fmax_kernel(const float* __restrict__ fm) {
    int gwarp = (blockIdx.x * blockDim.x + threadIdx.x) >> 5;
    int lane = threadIdx.x & 31;
    if (gwarp >= NPOS) return;
    const float4* p = reinterpret_cast<const float4*>(fm + (size_t)gwarp * CC);
    float m = -INFINITY;
#pragma unroll
    for (int i = 0; i < 4; ++i) {
        float4 v = p[lane + 32 * i];
        m = fmaxf(m, fmaxf(fmaxf(v.x, v.y), fmaxf(v.z, v.w)));
    }
#pragma unroll
    for (int o = 16; o; o >>= 1)
        m = fmaxf(m, __shfl_xor_sync(0xffffffffu, m, o));
    if (lane == 0) g_fmax[gwarp] = m;
}

// ---------------------------------------------------------------------------
// Kernel 2: one thread per (roi, bin). Scans its bin region of g_fmax (L2-hot)
// and writes the bin max to g_pool. 14700 threads total, no barriers.
// ---------------------------------------------------------------------------
__global__ void __launch_bounds__(256) pool_kernel(const float* __restrict__ rois) {
    int i = blockIdx.x * blockDim.x + threadIdx.x;
    if (i >= NROIS * NBINS) return;
    int roi = i / NBINS;
    int bin = i - roi * NBINS;
    int ph = bin / POOLK;
    int pw = bin - ph * POOLK;

    const float* r = rois + roi * 5;
    // truncation matches astype(int32) for nonneg; *0.0625f exact (== /16)
    int x1 = (int)(r[1] * 0.0625f);
    int y1 = (int)(r[2] * 0.0625f);
    int x2 = (int)(r[3] * 0.0625f);
    int y2 = (int)(r[4] * 0.0625f);
    int rh = y2 - y1 + 1;
    int rw = x2 - x1 + 1;

    int hs = min(max(y1 + (ph * rh) / POOLK, 0), HH);
    int he = min(max(y1 + ((ph + 1) * rh + POOLK - 1) / POOLK, 0), HH);
    int ws = min(max(x1 + (pw * rw) / POOLK, 0), WW);
    int we = min(max(x1 + ((pw + 1) * rw + POOLK - 1) / POOLK, 0), WW);

    float m = -INFINITY;
    for (int h = hs; h < he; ++h) {
        const float* row = g_fmax + h * WW;
        for (int w = ws; w < we; ++w) m = fmaxf(m, __ldg(row + w));
    }
    g_pool[i] = m;
}

// ---------------------------------------------------------------------------
// Kernel 3: pure broadcast-store. One float4 per thread, fully coalesced.
// Bin value is uniform across 128 consecutive threads -> L1-broadcast load.
// ---------------------------------------------------------------------------
__global__ void __launch_bounds__(256) bcast_kernel(float* __restrict__ out) {
    int idx = blockIdx.x * blockDim.x + threadIdx.x;  // float4 index
    // total = NROIS*NBINS*(CC/4) = 1,881,600 ; grid sized exactly, no guard needed
    float v = __ldg(g_pool + (idx >> 7));             // idx / (CC/4)
    reinterpret_cast<float4*>(out)[idx] = make_float4(v, v, v, v);
}

extern "C" void kernel_launch(void* const* d_in, const int* in_sizes, int n_in,
                              void* d_out, int out_size) {
    const float* rois = (const float*)d_in[0];
    const float* fm = (const float*)d_in[1];
    if (n_in >= 2 && in_sizes[0] > in_sizes[1]) {
        rois = (const float*)d_in[1];
        fm = (const float*)d_in[0];
    }
    float* out = (float*)d_out;

    const int threads = 256;
    fmax_kernel<<<(NPOS * 32 + threads - 1) / threads, threads>>>(fm);
    pool_kernel<<<(NROIS * NBINS + threads - 1) / threads, threads>>>(rois);

    const int n4 = NROIS * NBINS * (CC / 4);  // 1,881,600 = 7350 * 256
    bcast_kernel<<<n4 / threads, threads>>>(out);
}

// round 4
// speedup vs baseline: 1.1779x; 1.1779x over previous
#include <cuda_runtime.h>
#include <math.h>

#define POOLK 7
#define HH 50
#define WW 50
#define CC 512
#define NROIS 300
#define NPOS (HH * WW)
#define NBINS (POOLK * POOLK)

// Device-global scratch (no allocations allowed).
__device__ float g_fmax[NPOS];  // 10 KB channel-max map, L2-resident

// ---------------------------------------------------------------------------
// Kernel 1: fmax[h][w] = max_c feature_maps[h][w][c]
// 128 threads per spatial position (1 float4 each) -> 320K threads, high occ.
// Warp shfl-reduce, then 4 warp-partials combined via shared.
// ---------------------------------------------------------------------------
__global__ void __launch_bounds__(256) fmax_kernel(const float* __restrict__ fm) {
    const int gid = blockIdx.x * 256 + threadIdx.x;
    const int pos = gid >> 7;           // position index (grid sized exactly)
    const int t = threadIdx.x & 127;    // thread within position group
    const int grp = threadIdx.x >> 7;   // 0 or 1: position group within block
    const int w4 = (threadIdx.x >> 5) & 3;  // warp within group
    const int lane = threadIdx.x & 31;

    const float4 v = reinterpret_cast<const float4*>(fm + (size_t)pos * CC)[t];
    float m = fmaxf(fmaxf(v.x, v.y), fmaxf(v.z, v.w));
#pragma unroll
    for (int o = 16; o; o >>= 1)
        m = fmaxf(m, __shfl_xor_sync(0xffffffffu, m, o));

    __shared__ float part[2][4];
    if (lane == 0) part[grp][w4] = m;
    __syncthreads();
    if (t == 0)
        g_fmax[pos] = fmaxf(fmaxf(part[grp][0], part[grp][1]),
                            fmaxf(part[grp][2], part[grp][3]));
}

// ---------------------------------------------------------------------------
// Kernel 2: one block per (roi, ph). Warps 0..6 compute bin maxima for pw=0..6
// via parallel-lane loads of the bin region (<= ~25 elems) + shfl reduce.
// Then all 256 threads broadcast-write 7*512 floats (896 float4, coalesced).
// ---------------------------------------------------------------------------
__global__ void __launch_bounds__(256) roi_kernel(const float* __restrict__ rois,
                                                  float* __restrict__ out) {
    const int roi = blockIdx.x / POOLK;
    const int ph = blockIdx.x - roi * POOLK;

    const float* r = rois + roi * 5;
    // truncation matches astype(int32) for nonneg; *0.0625f exact (== /16)
    const int x1 = (int)(r[1] * 0.0625f);
    const int y1 = (int)(r[2] * 0.0625f);
    const int x2 = (int)(r[3] * 0.0625f);
    const int y2 = (int)(r[4] * 0.0625f);
    const int rh = y2 - y1 + 1;
    const int rw = x2 - x1 + 1;

    const int hs = min(max(y1 + (ph * rh) / POOLK, 0), HH);
    const int he = min(max(y1 + ((ph + 1) * rh + POOLK - 1) / POOLK, 0), HH);

    __shared__ float sbin[POOLK];
    const int wid = threadIdx.x >> 5;
    const int lane = threadIdx.x & 31;

    if (wid < POOLK) {
        const int pw = wid;
        const int ws = min(max(x1 + (pw * rw) / POOLK, 0), WW);
        const int we = min(max(x1 + ((pw + 1) * rw + POOLK - 1) / POOLK, 0), WW);
        const int nh = he - hs;
        const int nw = we - ws;
        const int cnt = (nh > 0 && nw > 0) ? nh * nw : 0;
        float m = -INFINITY;
        for (int e = lane; e < cnt; e += 32) {
            const int dh = e / nw;
            const int dw = e - dh * nw;
            m = fmaxf(m, __ldg(g_fmax + (hs + dh) * WW + (ws + dw)));
        }
#pragma unroll
        for (int o = 16; o; o >>= 1)
            m = fmaxf(m, __shfl_xor_sync(0xffffffffu, m, o));
        if (lane == 0) sbin[pw] = m;
    }
    __syncthreads();

    // Write 7 bins * 512 ch = 896 float4, coalesced. v uniform per 128 threads.
    float4* o = reinterpret_cast<float4*>(out) + (size_t)blockIdx.x * POOLK * (CC / 4);
    const int n4 = POOLK * (CC / 4);  // 896
    for (int idx = threadIdx.x; idx < n4; idx += 256) {
        const float v = sbin[idx >> 7];
        o[idx] = make_float4(v, v, v, v);
    }
}

extern "C" void kernel_launch(void* const* d_in, const int* in_sizes, int n_in,
                              void* d_out, int out_size) {
    const float* rois = (const float*)d_in[0];
    const float* fm = (const float*)d_in[1];
    if (n_in >= 2 && in_sizes[0] > in_sizes[1]) {
        rois = (const float*)d_in[1];
        fm = (const float*)d_in[0];
    }
    float* out = (float*)d_out;

    fmax_kernel<<<(NPOS * 128) / 256, 256>>>(fm);            // 1250 blocks
    roi_kernel<<<NROIS * POOLK, 256>>>(rois, out);           // 2100 blocks
}